// round 15
// baseline (speedup 1.0000x reference)
#include <cuda_runtime.h>

#define NROWS 2048
#define KDIM  1024
#define KCLI  64
#define PADROWS (NROWS + 128)   // tile loader may over-read past last class
#define NWORKERS 444            // 148 SMs x 3 co-resident blocks

// -------- device scratch (statics kept at the ~9.5MB profile) ----
static __device__ float g_gim[PADROWS * KDIM];    // gathered normalized phi_im
static __device__ float g_gcli[PADROWS * KCLI];   // gathered normalized phi_cli
static __device__ int   g_rows[NROWS];            // global slot -> original row
static __device__ int   g_cnt[3], g_off[3], g_cursor[3];
static __device__ int   g_cid[NROWS], g_slot[NROWS];
static __device__ unsigned long long g_min6[6];
static __device__ int   g_work;                   // work-queue cursor
static __device__ int   g_segN[9], g_segNX[9];    // items + x-tiles per segment
static __device__ int   g_tot;                    // total work items

__device__ __forceinline__ unsigned f2o(float f) {
    unsigned u = __float_as_uint(f);
    return (u & 0x80000000u) ? ~u : (u | 0x80000000u);
}
__device__ __forceinline__ float o2f(unsigned o) {
    unsigned u = (o & 0x80000000u) ? (o & 0x7fffffffu) : ~o;
    return __uint_as_float(u);
}
#define INF_KEY 0xFF80000000000000ull

__device__ __constant__ int c_cA[3] = {0, 0, 1};
__device__ __constant__ int c_cB[3] = {1, 2, 2};

// packed f32x2 helpers (sm_103a dual-lane fp32 FMA; only reachable via PTX)
__device__ __forceinline__ unsigned long long pack2(float lo, float hi) {
    unsigned long long r;
    asm("mov.b64 %0, {%1, %2};" : "=l"(r) : "f"(lo), "f"(hi));
    return r;
}
__device__ __forceinline__ void fma2(unsigned long long& d,
                                     unsigned long long a, unsigned long long b) {
    asm("fma.rn.f32x2 %0, %1, %2, %0;" : "+l"(d) : "l"(a), "l"(b));
}
__device__ __forceinline__ void unpack2(unsigned long long v, float& lo, float& hi) {
    asm("mov.b64 {%0, %1}, %2;" : "=f"(lo), "=f"(hi) : "l"(v));
}

// ---------------------------------------------------------------------------
__global__ void prep_kernel(const int* __restrict__ tw, const int* __restrict__ trw) {
    __shared__ int acc[256];
    int tid = threadIdx.x;
    if (tid < 6) g_min6[tid] = INF_KEY;
    if (tid < 3) g_cnt[tid] = 0;
    if (tid == 0) g_work = 0;

    // int64 vs int32 layout detection (t values in [0,3))
    int o = 0;
    for (int i = tid; i < NROWS; i += 256) o |= tw[2 * i + 1];
    acc[tid] = o;
    __syncthreads();
    for (int s = 128; s > 0; s >>= 1) {
        if (tid < s) acc[tid] |= acc[tid + s];
        __syncthreads();
    }
    bool is64 = (acc[0] == 0);

    for (int i = tid; i < NROWS; i += 256) {
        int t1 = is64 ? tw[4 * i + 2] : tw[2 * i + 1];
        int tr = is64 ? trw[2 * i]    : trw[i];
        int c = -1;
        if (t1 == 0 && tr == 1) c = 0;
        else if (t1 == 1)       c = 1;
        else if (t1 == 2)       c = 2;
        g_cid[i] = c;
        if (c >= 0) atomicAdd(&g_cnt[c], 1);
    }
    __syncthreads();

    if (tid == 0) {
        g_off[0] = 0; g_off[1] = g_cnt[0]; g_off[2] = g_cnt[0] + g_cnt[1];
        g_cursor[0] = g_off[0]; g_cursor[1] = g_off[1]; g_cursor[2] = g_off[2];
        // work-queue segments: 0..5 heavy (combo=s>>1, split=s&1), 6..8 light
        int tot = 0;
        for (int s = 0; s < 9; s++) {
            int combo = (s < 6) ? (s >> 1) : (s - 6);
            int na = g_cnt[c_cA[combo]], nb = g_cnt[c_cB[combo]];
            int ny = (na + 127) / 128, nx = (nb + 63) / 64;
            g_segNX[s] = nx;
            g_segN[s] = nx * ny;
            tot += nx * ny;
        }
        g_tot = tot;
    }
    __syncthreads();

    for (int i = tid; i < NROWS; i += 256) {
        int c = g_cid[i];
        if (c >= 0) {
            int s2 = atomicAdd(&g_cursor[c], 1);
            g_rows[s2] = i;
            g_slot[i] = s2;
        }
    }
}

// ---------------------------------------------------------------------------
__global__ void norm_gather(const float* __restrict__ im, const float* __restrict__ cli) {
    int row = blockIdx.x;
    int c = g_cid[row];
    if (c < 0) return;
    int slot = g_slot[row];
    int tid = threadIdx.x;
    __shared__ float red[256];

    float4 v = ((const float4*)(im + (size_t)row * KDIM))[tid];
    red[tid] = v.x * v.x + v.y * v.y + v.z * v.z + v.w * v.w;
    __syncthreads();
    for (int s = 128; s > 0; s >>= 1) {
        if (tid < s) red[tid] += red[tid + s];
        __syncthreads();
    }
    float inv = 1.0f / fmaxf(sqrtf(red[0]), 1e-12f);
    ((float4*)(g_gim + (size_t)slot * KDIM))[tid] =
        make_float4(v.x * inv, v.y * inv, v.z * inv, v.w * inv);
    __syncthreads();

    float cv = (tid < KCLI) ? cli[row * KCLI + tid] : 0.0f;
    red[tid] = cv * cv;
    __syncthreads();
    for (int s = 128; s > 0; s >>= 1) {
        if (tid < s) red[tid] += red[tid + s];
        __syncthreads();
    }
    float inv2 = 1.0f / fmaxf(sqrtf(red[0]), 1e-12f);
    if (tid < KCLI) g_gcli[slot * KCLI + tid] = cv * inv2;
}

// ---------------------------------------------------------------------------
__global__ void zero_out(float* __restrict__ out, int n) {
    int stride = gridDim.x * blockDim.x;
    int n4 = n / 4;
    for (int i = blockIdx.x * blockDim.x + threadIdx.x; i < n4; i += stride)
        ((float4*)out)[i] = make_float4(0.f, 0.f, 0.f, 0.f);
    int tail = n4 * 4 + blockIdx.x * blockDim.x + threadIdx.x;
    if (tail < n) out[tail] = 0.f;
}

// ---------------------------------------------------------------------------
// 128x64 tile, 8x4 micro (as 4x4 f32x2 pairs over i), 256 threads, BK=16.
// Double-buffered smem; fma.rn.f32x2 inner loop.
// ---------------------------------------------------------------------------
__device__ __forceinline__ void tile_gemm(
    const float* __restrict__ A, const float* __restrict__ B, int K,
    int kbeg, int kend, unsigned long long (&acc2)[4][4],
    float (*As)[16][128], float (*Bs)[16][64], int tid)
{
    const int lr = tid >> 2;        // 0..63  (A rows lr, lr+64; B row lr)
    const int lk = (tid & 3) * 4;   // k offset 0,4,8,12
    const int tx = tid & 15;        // col group (4 cols)
    const int ty = tid >> 4;        // row group (8 rows)

    float4 a0 = *(const float4*)&A[(size_t)lr        * K + kbeg + lk];
    float4 a1 = *(const float4*)&A[(size_t)(lr + 64) * K + kbeg + lk];
    float4 b0 = *(const float4*)&B[(size_t)lr        * K + kbeg + lk];
    As[0][lk + 0][lr] = a0.x; As[0][lk + 1][lr] = a0.y;
    As[0][lk + 2][lr] = a0.z; As[0][lk + 3][lr] = a0.w;
    As[0][lk + 0][lr + 64] = a1.x; As[0][lk + 1][lr + 64] = a1.y;
    As[0][lk + 2][lr + 64] = a1.z; As[0][lk + 3][lr + 64] = a1.w;
    Bs[0][lk + 0][lr] = b0.x; Bs[0][lk + 1][lr] = b0.y;
    Bs[0][lk + 2][lr] = b0.z; Bs[0][lk + 3][lr] = b0.w;
    __syncthreads();

    int buf = 0;
    for (int kt = kbeg; kt < kend; kt += 16) {
        const bool more = (kt + 16 < kend);
        if (more) {
            a0 = *(const float4*)&A[(size_t)lr        * K + kt + 16 + lk];
            a1 = *(const float4*)&A[(size_t)(lr + 64) * K + kt + 16 + lk];
            b0 = *(const float4*)&B[(size_t)lr        * K + kt + 16 + lk];
        }

#pragma unroll
        for (int k = 0; k < 16; k++) {
            const ulonglong2* ap = (const ulonglong2*)&As[buf][k][ty * 8];
            ulonglong2 av0 = ap[0], av1 = ap[1];
            unsigned long long a2[4] = {av0.x, av0.y, av1.x, av1.y};
            float4 br = *(const float4*)&Bs[buf][k][tx * 4];
            unsigned long long bb[4] = {
                pack2(br.x, br.x), pack2(br.y, br.y),
                pack2(br.z, br.z), pack2(br.w, br.w)};
#pragma unroll
            for (int i2 = 0; i2 < 4; i2++)
#pragma unroll
                for (int j = 0; j < 4; j++)
                    fma2(acc2[i2][j], a2[i2], bb[j]);
        }

        if (more) {
            const int nb = buf ^ 1;
            As[nb][lk + 0][lr] = a0.x; As[nb][lk + 1][lr] = a0.y;
            As[nb][lk + 2][lr] = a0.z; As[nb][lk + 3][lr] = a0.w;
            As[nb][lk + 0][lr + 64] = a1.x; As[nb][lk + 1][lr + 64] = a1.y;
            As[nb][lk + 2][lr + 64] = a1.z; As[nb][lk + 3][lr + 64] = a1.w;
            Bs[nb][lk + 0][lr] = b0.x; Bs[nb][lk + 1][lr] = b0.y;
            Bs[nb][lk + 2][lr] = b0.z; Bs[nb][lk + 3][lr] = b0.w;
            __syncthreads();
            buf = nb;
        }
    }
}

__device__ __forceinline__ void unpack_acc(
    const unsigned long long (&acc2)[4][4], float (&acc)[8][4])
{
#pragma unroll
    for (int i2 = 0; i2 < 4; i2++)
#pragma unroll
        for (int j = 0; j < 4; j++)
            unpack2(acc2[i2][j], acc[2 * i2][j], acc[2 * i2 + 1][j]);
}

// ---------------------------------------------------------------------------
// Persistent work-queue GEMM: NWORKERS blocks pull tiles from g_work.
// Segments 0..5: im GEMM (combo=s>>1, split=s&1) -> 2-addend atomicAdd
// (bitwise deterministic on zeroed cells). Segments 6..8: cli GEMM ->
// direct store + argmin. Heavy segments first => light tiles fill the tail.
// ---------------------------------------------------------------------------
__global__ __launch_bounds__(256, 3)
void gemm_all(float* __restrict__ out) {
    __shared__ float As[2][16][128];
    __shared__ float Bs[2][16][64];
    __shared__ int s_w;
    const int tid = threadIdx.x;
    const int tx = tid & 15, ty = tid >> 4;

    for (;;) {
        if (tid == 0) s_w = atomicAdd(&g_work, 1);
        __syncthreads();           // broadcasts s_w; also fences As/Bs reuse
        const int w = s_w;
        if (w >= g_tot) return;

        // decode segment
        int s = 0, rem = w;
        while (rem >= g_segN[s]) { rem -= g_segN[s]; s++; }
        const int nx = g_segNX[s];
        const int bx = rem % nx, by = rem / nx;
        const int combo = (s < 6) ? (s >> 1) : (s - 6);
        const int ca = c_cA[combo], cb = c_cB[combo];
        const int na = g_cnt[ca], nb = g_cnt[cb];
        const int offA = g_off[ca], offB = g_off[cb];

        unsigned long long acc2[4][4];
#pragma unroll
        for (int i = 0; i < 4; i++)
#pragma unroll
            for (int j = 0; j < 4; j++) acc2[i][j] = 0ull;
        float acc[8][4];

        int gc[4]; bool cv[4];
#pragma unroll
        for (int j = 0; j < 4; j++) {
            int c = bx * 64 + tx * 4 + j;
            cv[j] = c < nb;
            gc[j] = cv[j] ? g_rows[offB + c] : 0;
        }

        if (s < 6) {
            const int split = s & 1;
            const float* A = g_gim + (size_t)(offA + by * 128) * KDIM;
            const float* B = g_gim + (size_t)(offB + bx * 64) * KDIM;
            tile_gemm(A, B, KDIM, split * 512, split * 512 + 512, acc2, As, Bs, tid);
            unpack_acc(acc2, acc);

            float* __restrict__ op = out + (size_t)combo * NROWS * NROWS;
#pragma unroll
            for (int i = 0; i < 8; i++) {
                int r = by * 128 + ty * 8 + i;
                if (r >= na) continue;
                unsigned rbase = (unsigned)g_rows[offA + r] * NROWS;
#pragma unroll
                for (int j = 0; j < 4; j++) {
                    if (!cv[j]) continue;
                    atomicAdd(&op[rbase + (unsigned)gc[j]], acc[i][j]);
                }
            }
        } else {
            const float* A = g_gcli + (size_t)(offA + by * 128) * KCLI;
            const float* B = g_gcli + (size_t)(offB + bx * 64) * KCLI;
            tile_gemm(A, B, KCLI, 0, KCLI, acc2, As, Bs, tid);
            unpack_acc(acc2, acc);

            float* __restrict__ op = out + (size_t)(3 + combo) * NROWS * NROWS;
            unsigned long long best = INF_KEY;
#pragma unroll
            for (int i = 0; i < 8; i++) {
                int r = by * 128 + ty * 8 + i;
                if (r >= na) continue;
                unsigned rbase = (unsigned)g_rows[offA + r] * NROWS;
#pragma unroll
                for (int j = 0; j < 4; j++) {
                    if (!cv[j]) continue;
                    float sv = acc[i][j];
                    unsigned flat = rbase + (unsigned)gc[j];
                    op[flat] = sv;
                    unsigned long long key = ((unsigned long long)f2o(sv) << 32) | flat;
                    if (key < best) best = key;
                }
            }
#pragma unroll
            for (int off = 16; off > 0; off >>= 1) {
                unsigned long long o = __shfl_down_sync(0xffffffffu, best, off);
                if (o < best) best = o;
            }
            if ((tid & 31) == 0 && best != INF_KEY)
                atomicMin(&g_min6[3 + combo], best);
        }
    }
}

// ---------------------------------------------------------------------------
// argmin over the summed im-combo cells (reads deterministic final values)
// ---------------------------------------------------------------------------
__global__ __launch_bounds__(256)
void argmin_im(const float* __restrict__ out) {
    const int combo = blockIdx.z;
    const int ca = c_cA[combo], cb = c_cB[combo];
    const int na = g_cnt[ca], nb = g_cnt[cb];
    const int bx = blockIdx.x, by = blockIdx.y;
    if (by * 128 >= na || bx * 128 >= nb) return;

    const int offA = g_off[ca], offB = g_off[cb];
    const int tid = threadIdx.x;
    const int tx = tid & 15, ty = tid >> 4;

    int gc[8]; bool cv[8];
#pragma unroll
    for (int j = 0; j < 8; j++) {
        int c = bx * 128 + tx * 8 + j;
        cv[j] = c < nb;
        gc[j] = cv[j] ? g_rows[offB + c] : 0;
    }

    const float* __restrict__ op = out + (size_t)combo * NROWS * NROWS;
    unsigned long long best = INF_KEY;
#pragma unroll
    for (int i = 0; i < 8; i++) {
        int r = by * 128 + ty * 8 + i;
        if (r >= na) continue;
        unsigned rbase = (unsigned)g_rows[offA + r] * NROWS;
#pragma unroll
        for (int j = 0; j < 8; j++) {
            if (!cv[j]) continue;
            unsigned flat = rbase + (unsigned)gc[j];
            float s = op[flat];
            unsigned long long key = ((unsigned long long)f2o(s) << 32) | flat;
            if (key < best) best = key;
        }
    }
#pragma unroll
    for (int off = 16; off > 0; off >>= 1) {
        unsigned long long o = __shfl_down_sync(0xffffffffu, best, off);
        if (o < best) best = o;
    }
    if ((tid & 31) == 0 && best != INF_KEY)
        atomicMin(&g_min6[combo], best);
}

// ---------------------------------------------------------------------------
__global__ void finalize_kernel(float* __restrict__ out) {
    int p = threadIdx.x;
    if (p < 6) {
        unsigned long long k = g_min6[p];
        size_t base = (size_t)6 * NROWS * NROWS;
        out[base + p] = o2f((unsigned)(k >> 32));
        unsigned flat = (unsigned)k;
        out[base + 6 + 2 * p]     = (float)(flat / NROWS);
        out[base + 6 + 2 * p + 1] = (float)(flat % NROWS);
    }
}

// ---------------------------------------------------------------------------
extern "C" void kernel_launch(void* const* d_in, const int* in_sizes, int n_in,
                              void* d_out, int out_size) {
    const float* phi_im  = (const float*)d_in[0];
    const float* phi_cli = (const float*)d_in[1];
    const int*   tw      = (const int*)d_in[2];
    const int*   trw     = (const int*)d_in[3];
    float* out = (float*)d_out;

    prep_kernel<<<1, 256>>>(tw, trw);
    norm_gather<<<NROWS, 256>>>(phi_im, phi_cli);
    zero_out<<<2048, 256>>>(out, out_size);

    gemm_all<<<NWORKERS, 256>>>(out);

    dim3 agrid(16, 16, 3);
    argmin_im<<<agrid, 256>>>(out);

    finalize_kernel<<<1, 32>>>(out);
}